// round 7
// baseline (speedup 1.0000x reference)
#include <cuda_runtime.h>
#include <math_constants.h>
#include <cstdint>

// Problem constants
#define NTOK 16384
#define DIM  256
#define KC   8192
#define DECAYF 0.99f
#define OMDF   0.01f
#define EPSF   1e-5f
#define CWF    0.25f

// GEMM tiling
#define BM 128
#define BN 128
#define EBUF 8192                 // floats per E fragment buffer (8 ks * 8 gp * 32 lane * 4)
#define AFRAG (8 * 32 * 32 * 4)   // A fragment layout floats (32768 = 128KB)
#define ZPITCH 132                // z staging pitch (conflict-free transform reads)
#define ESIZE 16896               // staging/merge region floats (>= 2*EBUF, >= 128*ZPITCH, >= 8192 ull/2)

// ---------------- scratch ------------------------------------------------
__device__ float g_cluster[KC];
__device__ float g_embed_sum[KC * DIM];
__device__ float g_esq[KC];
__device__ float g_esqh[KC];      // -0.5 * esq
__device__ int   g_indices[NTOK];
__device__ int   g_cand[4 * NTOK];
__device__ float g_loss;

// ---------------- helpers -------------------------------------------------
__device__ __forceinline__ unsigned tf32_bits(float x) {
    unsigned r;
    asm("cvt.rna.tf32.f32 %0, %1;" : "=r"(r) : "f"(x));
    return r;
}
__device__ __forceinline__ unsigned int ford(float f) {
    unsigned int u = __float_as_uint(f);
    return (u & 0x80000000u) ? ~u : (u | 0x80000000u);  // order-preserving
}
__device__ __forceinline__ void mma_tf32(float* c, const unsigned* a, const unsigned* b) {
    asm volatile(
        "mma.sync.aligned.m16n8k8.row.col.f32.tf32.tf32.f32 "
        "{%0,%1,%2,%3}, {%4,%5,%6,%7}, {%8,%9}, {%0,%1,%2,%3};"
        : "+f"(c[0]), "+f"(c[1]), "+f"(c[2]), "+f"(c[3])
        : "r"(a[0]), "r"(a[1]), "r"(a[2]), "r"(a[3]), "r"(b[0]), "r"(b[1]));
}
#define INSERT4(T, key) do { \
    if ((key) > (T)[3]) { \
        if ((key) > (T)[0])      { (T)[3]=(T)[2]; (T)[2]=(T)[1]; (T)[1]=(T)[0]; (T)[0]=(key); } \
        else if ((key) > (T)[1]) { (T)[3]=(T)[2]; (T)[2]=(T)[1]; (T)[1]=(key); } \
        else if ((key) > (T)[2]) { (T)[3]=(T)[2]; (T)[2]=(key); } \
        else                     { (T)[3]=(key); } \
    } } while (0)

// ---------------- init ----------------------------------------------------
__global__ void init_kernel() {
    int i = blockIdx.x * blockDim.x + threadIdx.x;
    if (i < KC * DIM) g_embed_sum[i] = 0.0f;
    if (i < KC)       g_cluster[i] = 0.0f;
    if (i == 0)       g_loss = 0.0f;
}

// ---------------- e_sq (frozen numerics) + (-e_sq/2) ----------------------
__global__ void esq_kernel(const float* __restrict__ emb) {
    int gw   = (blockIdx.x * blockDim.x + threadIdx.x) >> 5;
    int lane = threadIdx.x & 31;
    if (gw >= KC) return;
    const float4* e4 = reinterpret_cast<const float4*>(emb + (size_t)gw * DIM);
    float4 a = e4[lane * 2];
    float4 b = e4[lane * 2 + 1];
    float s = a.x*a.x + a.y*a.y + a.z*a.z + a.w*a.w
            + b.x*b.x + b.y*b.y + b.z*b.z + b.w*b.w;
    #pragma unroll
    for (int o = 16; o; o >>= 1) s += __shfl_xor_sync(0xffffffffu, s, o);
    if (lane == 0) { g_esq[gw] = s; g_esqh[gw] = -0.5f * s; }
}

// ---------------- mma.sync tf32 argmin (top-4 candidates) -----------------
// D = (-esq/2) + z.e ; argmax D == argmin distance. 8 warps = 2(M) x 4(N).
// E staged directly into B-fragment layout: one LDS.128 = two N-fragments.
__device__ __forceinline__ void stage_bfrag(float* __restrict__ buf,
                                            int code, int dq, float4 v) {
    // dims d0 = dq*4 .. dq*4+3 within 64-dim chunk
    int ks    = dq >> 1;            // 8-dim k-step
    int half  = dq & 1;             // b0 (k 0..3) vs b1 (k 4..7)
    int gp    = code >> 4;          // fragment-group pair
    int gcomp = (code >> 3) & 1;    // even/odd fragment within pair
    int comp  = gcomp * 2 + half;   // component within float4
    float* base = buf + (((ks * 8 + gp) * 32 + (code & 7) * 4) << 2) + comp;
    base[0]  = __uint_as_float(tf32_bits(v.x));
    base[4]  = __uint_as_float(tf32_bits(v.y));
    base[8]  = __uint_as_float(tf32_bits(v.z));
    base[12] = __uint_as_float(tf32_bits(v.w));
}

__global__ __launch_bounds__(256, 1)
void argmin_kernel(const float* __restrict__ z, const float* __restrict__ emb) {
    extern __shared__ float sm[];
    float* afr = sm;              // A fragments [mf 8][ks 32][lane 32][4]
    float* es  = sm + AFRAG;      // 2 x EBUF (E frags); reused for z staging / merge

    const int tid  = threadIdx.x;
    const int lane = tid & 31;
    const int warp = tid >> 5;
    const int wr   = warp >> 2;   // warp row (0..1) -> 64 token rows
    const int wn   = warp & 3;    // warp col (0..3) -> 32 codes
    const int m0   = blockIdx.x * BM;

    // ---- stage z into tf32 A-fragment layout (two 128-dim halves) ----
    for (int h = 0; h < 2; h++) {
        for (int i = tid; i < 128 * 32; i += 256) {
            int row = i >> 5, dq = i & 31;
            float4 v = __ldg(reinterpret_cast<const float4*>(
                z + (size_t)(m0 + row) * DIM + h * 128 + dq * 4));
            float* d = es + row * ZPITCH + dq * 4;
            d[0] = __uint_as_float(tf32_bits(v.x));
            d[1] = __uint_as_float(tf32_bits(v.y));
            d[2] = __uint_as_float(tf32_bits(v.z));
            d[3] = __uint_as_float(tf32_bits(v.w));
        }
        __syncthreads();
        for (int s = tid; s < 4096; s += 256) {
            int ls = s & 31, ksl = (s >> 5) & 15, mf = s >> 9;
            int r = ls >> 2, cc = ls & 3;
            const float* zb  = es + (mf * 16 + r) * ZPITCH;
            const float* zb8 = zb + 8 * ZPITCH;
            int d0 = ksl * 8 + cc;
            float4 w = make_float4(zb[d0], zb8[d0], zb[d0 + 4], zb8[d0 + 4]);
            *reinterpret_cast<float4*>(
                afr + ((mf * 32 + h * 16 + ksl) * 32 + ls) * 4) = w;
        }
        __syncthreads();
    }

    unsigned long long top[8][4];
    #pragma unroll
    for (int i = 0; i < 8; i++)
        #pragma unroll
        for (int j = 0; j < 4; j++) top[i][j] = 0ULL;

    #pragma unroll 1
    for (int nt = 0; nt < KC / BN; nt++) {
        // init accumulators with -esq/2 (column-dependent)
        float acc[4][4][4];
        #pragma unroll
        for (int nfl = 0; nfl < 4; nfl++) {
            int j0 = nt * BN + wn * 32 + nfl * 8 + (lane & 3) * 2;
            float v0 = __ldg(&g_esqh[j0]), v1 = __ldg(&g_esqh[j0 + 1]);
            #pragma unroll
            for (int mfl = 0; mfl < 4; mfl++) {
                acc[mfl][nfl][0] = v0; acc[mfl][nfl][1] = v1;
                acc[mfl][nfl][2] = v0; acc[mfl][nfl][3] = v1;
            }
        }

        // stage k-chunk 0 (64 dims) into buffer 0
        #pragma unroll
        for (int it = 0; it < 8; it++) {
            int idx = tid + it * 256;
            int code = idx >> 4, dq = idx & 15;
            float4 v = __ldg(reinterpret_cast<const float4*>(
                emb + (size_t)(nt * BN + code) * DIM + dq * 4));
            stage_bfrag(es, code, dq, v);
        }
        __syncthreads();

        #pragma unroll 1
        for (int c = 0; c < 4; c++) {
            const int buf = c & 1;
            float4 pre[8];
            if (c < 3) {
                #pragma unroll
                for (int it = 0; it < 8; it++) {
                    int idx = tid + it * 256;
                    int code = idx >> 4, dq = idx & 15;
                    pre[it] = __ldg(reinterpret_cast<const float4*>(
                        emb + (size_t)(nt * BN + code) * DIM + (c + 1) * 64 + dq * 4));
                }
            }
            const float* eb = es + buf * EBUF;

            // register-double-buffered fragments across k-steps
            unsigned a[2][4][4], b[2][4][2];
            {
                const int ksg0 = c * 8;
                #pragma unroll
                for (int mfl = 0; mfl < 4; mfl++) {
                    float4 av = *reinterpret_cast<const float4*>(
                        afr + (((wr * 4 + mfl) * 32 + ksg0) * 32 + lane) * 4);
                    a[0][mfl][0] = __float_as_uint(av.x);
                    a[0][mfl][1] = __float_as_uint(av.y);
                    a[0][mfl][2] = __float_as_uint(av.z);
                    a[0][mfl][3] = __float_as_uint(av.w);
                }
                #pragma unroll
                for (int p = 0; p < 2; p++) {
                    float4 q = *reinterpret_cast<const float4*>(
                        eb + (((0 * 8 + wn * 2 + p) * 32 + lane) << 2));
                    b[0][2*p][0]   = __float_as_uint(q.x);
                    b[0][2*p][1]   = __float_as_uint(q.y);
                    b[0][2*p+1][0] = __float_as_uint(q.z);
                    b[0][2*p+1][1] = __float_as_uint(q.w);
                }
            }
            #pragma unroll
            for (int ks = 0; ks < 8; ks++) {
                const int cur = ks & 1, nxt = cur ^ 1;
                if (ks < 7) {
                    const int ksg = c * 8 + ks + 1;
                    #pragma unroll
                    for (int mfl = 0; mfl < 4; mfl++) {
                        float4 av = *reinterpret_cast<const float4*>(
                            afr + (((wr * 4 + mfl) * 32 + ksg) * 32 + lane) * 4);
                        a[nxt][mfl][0] = __float_as_uint(av.x);
                        a[nxt][mfl][1] = __float_as_uint(av.y);
                        a[nxt][mfl][2] = __float_as_uint(av.z);
                        a[nxt][mfl][3] = __float_as_uint(av.w);
                    }
                    #pragma unroll
                    for (int p = 0; p < 2; p++) {
                        float4 q = *reinterpret_cast<const float4*>(
                            eb + ((((ks + 1) * 8 + wn * 2 + p) * 32 + lane) << 2));
                        b[nxt][2*p][0]   = __float_as_uint(q.x);
                        b[nxt][2*p][1]   = __float_as_uint(q.y);
                        b[nxt][2*p+1][0] = __float_as_uint(q.z);
                        b[nxt][2*p+1][1] = __float_as_uint(q.w);
                    }
                }
                #pragma unroll
                for (int mfl = 0; mfl < 4; mfl++)
                    #pragma unroll
                    for (int nfl = 0; nfl < 4; nfl++)
                        mma_tf32(acc[mfl][nfl], a[cur][mfl], b[cur][nfl]);
            }

            if (c < 3) {
                float* d0 = es + (buf ^ 1) * EBUF;
                #pragma unroll
                for (int it = 0; it < 8; it++) {
                    int idx = tid + it * 256;
                    int code = idx >> 4, dq = idx & 15;
                    stage_bfrag(d0, code, dq, pre[it]);
                }
            }
            __syncthreads();
        }

        // per-tile epilogue: insert 64 scores into per-thread top-4
        #pragma unroll
        for (int mfl = 0; mfl < 4; mfl++)
            #pragma unroll
            for (int nfl = 0; nfl < 4; nfl++)
                #pragma unroll
                for (int j = 0; j < 4; j++) {
                    float v = acc[mfl][nfl][j];
                    int col = nt * BN + wn * 32 + nfl * 8 + (lane & 3) * 2 + (j & 1);
                    int rs  = mfl * 2 + (j >> 1);
                    unsigned long long key =
                        ((unsigned long long)ford(v) << 32) | (unsigned)col;
                    INSERT4(top[rs], key);
                }
    }

    // ---- cross-thread merge: red[(owner*4+j)*128 + row] ----
    __syncthreads();
    unsigned long long* red = reinterpret_cast<unsigned long long*>(es);
    const int owner = wn * 4 + (lane & 3);
    #pragma unroll
    for (int rs = 0; rs < 8; rs++) {
        int row = wr * 64 + (rs >> 1) * 16 + (rs & 1) * 8 + (lane >> 2);
        #pragma unroll
        for (int j = 0; j < 4; j++)
            red[(owner * 4 + j) * 128 + row] = top[rs][j];
    }
    __syncthreads();
    if (tid < 128) {
        unsigned long long t[4] = {0ULL, 0ULL, 0ULL, 0ULL};
        for (int i = 0; i < 64; i++) {
            unsigned long long k = red[i * 128 + tid];
            INSERT4(t, k);
        }
        int row = m0 + tid;
        g_cand[0 * NTOK + row] = (int)(t[0] & 0xffffffffu);
        g_cand[1 * NTOK + row] = (int)(t[1] & 0xffffffffu);
        g_cand[2 * NTOK + row] = (int)(t[2] & 0xffffffffu);
        g_cand[3 * NTOK + row] = (int)(t[3] & 0xffffffffu);
    }
}

// ---------------- rescore: warp per token, exact reference rounding -------
__global__ __launch_bounds__(256)
void rescore_kernel(const float* __restrict__ z, const float* __restrict__ emb) {
    const int w    = (blockIdx.x * blockDim.x + threadIdx.x) >> 5;
    const int lane = threadIdx.x & 31;
    if (w >= NTOK) return;
    const float* zr = z + (size_t)w * DIM;

    float zv[8];
    #pragma unroll
    for (int j = 0; j < 8; j++) zv[j] = __ldg(&zr[j * 32 + lane]);

    // z_sq: strict sequential fp32 in index order (frozen — matches reference)
    float S = 0.0f;
    #pragma unroll
    for (int j = 0; j < 8; j++)
        for (int ii = 0; ii < 32; ii++) {
            float v = __shfl_sync(0xffffffffu, zv[j], ii);
            S = __fadd_rn(S, __fmul_rn(v, v));
        }

    float bq = 0.0f; int bi = -1;
    #pragma unroll
    for (int c = 0; c < 4; c++) {
        int idx = g_cand[c * NTOK + w];
        const float* e = emb + (size_t)idx * DIM;
        double acc = 0.0;
        #pragma unroll
        for (int j = 0; j < 8; j++)
            acc += (double)zv[j] * (double)__ldg(&e[j * 32 + lane]);
        #pragma unroll
        for (int o = 16; o; o >>= 1)
            acc += __shfl_down_sync(0xffffffffu, acc, o);
        acc = __shfl_sync(0xffffffffu, acc, 0);
        float q = __fsub_rn(__fadd_rn(S, __ldg(&g_esq[idx])),
                            __fmul_rn(2.0f, (float)acc));
        if (bi < 0 || q < bq || (q == bq && idx < bi)) { bq = q; bi = idx; }
    }
    if (lane == 0) g_indices[w] = bi;
}

// ---------------- per-token epilogue --------------------------------------
__global__ void epilogue_kernel(const float* __restrict__ z,
                                const float* __restrict__ emb,
                                float* __restrict__ out_zq,
                                float* __restrict__ out_idx) {
    int gw   = (blockIdx.x * blockDim.x + threadIdx.x) >> 5;
    int lane = threadIdx.x & 31;
    if (gw >= NTOK) return;
    int idx = g_indices[gw];
    const float4* zr = reinterpret_cast<const float4*>(z   + (size_t)gw  * DIM);
    const float4* er = reinterpret_cast<const float4*>(emb + (size_t)idx * DIM);
    float4* o = reinterpret_cast<float4*>(out_zq + (size_t)gw * DIM);
    float* esum = g_embed_sum + (size_t)idx * DIM;
    float loss = 0.0f;
    #pragma unroll
    for (int j = lane; j < DIM / 4; j += 32) {
        float4 zv = zr[j], ev = er[j];
        float dx = ev.x - zv.x, dy = ev.y - zv.y, dz = ev.z - zv.z, dw = ev.w - zv.w;
        float4 q;
        q.x = zv.x + dx; q.y = zv.y + dy; q.z = zv.z + dz; q.w = zv.w + dw;
        o[j] = q;
        loss += dx * dx + dy * dy + dz * dz + dw * dw;
        atomicAdd(&esum[j * 4 + 0], zv.x);
        atomicAdd(&esum[j * 4 + 1], zv.y);
        atomicAdd(&esum[j * 4 + 2], zv.z);
        atomicAdd(&esum[j * 4 + 3], zv.w);
    }
    #pragma unroll
    for (int off = 16; off; off >>= 1) loss += __shfl_xor_sync(0xffffffffu, loss, off);
    if (lane == 0) {
        atomicAdd(&g_loss, loss);
        atomicAdd(&g_cluster[idx], 1.0f);
        out_idx[gw] = (float)idx;
    }
}

// ---------------- EMA finalize --------------------------------------------
__global__ void finalize_kernel(const float* __restrict__ ema_cs,
                                const float* __restrict__ ema_es,
                                float* __restrict__ out_emb,
                                float* __restrict__ out_ecs,
                                float* __restrict__ out_ees,
                                float* __restrict__ out_l1,
                                float* __restrict__ out_l2) {
    int i = blockIdx.x * blockDim.x + threadIdx.x;
    if (i < KC * DIM) {
        int k = i >> 8;
        float ncs = DECAYF * ema_cs[k] + OMDF * g_cluster[k];
        float nes = DECAYF * ema_es[i] + OMDF * g_embed_sum[i];
        out_ees[i] = nes;
        out_emb[i] = nes / (ncs + EPSF);
    }
    if (i < KC) {
        out_ecs[i] = DECAYF * ema_cs[i] + OMDF * g_cluster[i];
    }
    if (i == 0) {
        float L = CWF * (g_loss / (float)(NTOK * DIM));
        out_l1[0] = L;
        out_l2[0] = L;
    }
}

// ---------------- launch ---------------------------------------------------
extern "C" void kernel_launch(void* const* d_in, const int* in_sizes, int n_in,
                              void* d_out, int out_size) {
    const float* z      = (const float*)d_in[0];
    const float* emb    = (const float*)d_in[1];
    const float* ema_cs = (const float*)d_in[2];
    const float* ema_es = (const float*)d_in[3];
    float* out = (float*)d_out;

    float* out_zq  = out;
    float* out_idx = out_zq + (size_t)NTOK * DIM;
    float* out_l1  = out_idx + NTOK;
    float* out_l2  = out_l1 + 1;
    float* out_emb = out_l2 + 1;
    float* out_ecs = out_emb + (size_t)KC * DIM;
    float* out_ees = out_ecs + KC;

    const int smem = (AFRAG + ESIZE) * 4;   // 198656 bytes
    cudaFuncSetAttribute(argmin_kernel,
                         cudaFuncAttributeMaxDynamicSharedMemorySize, smem);

    init_kernel<<<(KC * DIM + 255) / 256, 256>>>();
    esq_kernel<<<(KC * 32 + 255) / 256, 256>>>(emb);
    argmin_kernel<<<NTOK / BM, 256, smem>>>(z, emb);
    rescore_kernel<<<(NTOK * 32) / 256, 256>>>(z, emb);
    epilogue_kernel<<<(NTOK * 32 + 255) / 256, 256>>>(z, emb, out_zq, out_idx);
    finalize_kernel<<<(KC * DIM + 255) / 256, 256>>>(ema_cs, ema_es, out_emb,
                                                     out_ecs, out_ees, out_l1, out_l2);
}

// round 9
// speedup vs baseline: 1.0005x; 1.0005x over previous
#include <cuda_runtime.h>
#include <math_constants.h>
#include <cstdint>

// Problem constants
#define NTOK 16384
#define DIM  256
#define KC   8192
#define DECAYF 0.99f
#define OMDF   0.01f
#define EPSF   1e-5f
#define CWF    0.25f

// GEMM tiling
#define BM 128
#define BN 128
#define EBUF 8192                 // floats per E fragment buffer (8 ks * 8 gp * 32 lane * 4)
#define AFRAG (8 * 32 * 32 * 4)   // A fragment layout floats (32768 = 128KB)
#define ZPITCH 132                // z staging pitch (conflict-free transform reads)
#define ESIZE 16896               // staging/merge region floats

// ---------------- scratch ------------------------------------------------
__device__ float g_cluster[KC];
__device__ float g_embed_sum[KC * DIM];
__device__ float g_esq[KC];
__device__ float g_esqh[KC];      // -0.5 * esq
__device__ int   g_indices[NTOK];
__device__ int   g_cand[4 * NTOK];
__device__ float g_loss;

// ---------------- helpers -------------------------------------------------
__device__ __forceinline__ unsigned tf32_bits(float x) {
    unsigned r;
    asm("cvt.rna.tf32.f32 %0, %1;" : "=r"(r) : "f"(x));
    return r;
}
__device__ __forceinline__ unsigned int ford(float f) {
    unsigned int u = __float_as_uint(f);
    return (u & 0x80000000u) ? ~u : (u | 0x80000000u);  // order-preserving
}
__device__ __forceinline__ void mma_tf32(float* c, const unsigned* a, const unsigned* b) {
    asm volatile(
        "mma.sync.aligned.m16n8k8.row.col.f32.tf32.tf32.f32 "
        "{%0,%1,%2,%3}, {%4,%5,%6,%7}, {%8,%9}, {%0,%1,%2,%3};"
        : "+f"(c[0]), "+f"(c[1]), "+f"(c[2]), "+f"(c[3])
        : "r"(a[0]), "r"(a[1]), "r"(a[2]), "r"(a[3]), "r"(b[0]), "r"(b[1]));
}
#define INSERT4(T, key) do { \
    if ((key) > (T)[3]) { \
        if ((key) > (T)[0])      { (T)[3]=(T)[2]; (T)[2]=(T)[1]; (T)[1]=(T)[0]; (T)[0]=(key); } \
        else if ((key) > (T)[1]) { (T)[3]=(T)[2]; (T)[2]=(T)[1]; (T)[1]=(key); } \
        else if ((key) > (T)[2]) { (T)[3]=(T)[2]; (T)[2]=(key); } \
        else                     { (T)[3]=(key); } \
    } } while (0)

// ---------------- init ----------------------------------------------------
__global__ void init_kernel() {
    int i = blockIdx.x * blockDim.x + threadIdx.x;
    if (i < KC * DIM) g_embed_sum[i] = 0.0f;
    if (i < KC)       g_cluster[i] = 0.0f;
    if (i == 0)       g_loss = 0.0f;
}

// ---------------- e_sq (frozen numerics) + (-e_sq/2) ----------------------
__global__ void esq_kernel(const float* __restrict__ emb) {
    int gw   = (blockIdx.x * blockDim.x + threadIdx.x) >> 5;
    int lane = threadIdx.x & 31;
    if (gw >= KC) return;
    const float4* e4 = reinterpret_cast<const float4*>(emb + (size_t)gw * DIM);
    float4 a = e4[lane * 2];
    float4 b = e4[lane * 2 + 1];
    float s = a.x*a.x + a.y*a.y + a.z*a.z + a.w*a.w
            + b.x*b.x + b.y*b.y + b.z*b.z + b.w*b.w;
    #pragma unroll
    for (int o = 16; o; o >>= 1) s += __shfl_xor_sync(0xffffffffu, s, o);
    if (lane == 0) { g_esq[gw] = s; g_esqh[gw] = -0.5f * s; }
}

// ---------------- mma.sync tf32 argmin (top-4 candidates) -----------------
// D = (-esq/2) + z.e ; argmax D == argmin distance. 8 warps = 2(M) x 4(N).
// E staged directly into B-fragment layout: one LDS.128 = two N-fragments.
__device__ __forceinline__ void stage_bfrag(float* __restrict__ buf,
                                            int code, int dq, float4 v) {
    int ks    = dq >> 1;            // 8-dim k-step
    int half  = dq & 1;             // b0 (k 0..3) vs b1 (k 4..7)
    int gp    = code >> 4;          // fragment-group pair
    int gcomp = (code >> 3) & 1;    // even/odd fragment within pair
    int comp  = gcomp * 2 + half;   // component within float4
    float* base = buf + (((ks * 8 + gp) * 32 + (code & 7) * 4) << 2) + comp;
    base[0]  = __uint_as_float(tf32_bits(v.x));
    base[4]  = __uint_as_float(tf32_bits(v.y));
    base[8]  = __uint_as_float(tf32_bits(v.z));
    base[12] = __uint_as_float(tf32_bits(v.w));
}

__global__ __launch_bounds__(256, 1)
void argmin_kernel(const float* __restrict__ z, const float* __restrict__ emb) {
    extern __shared__ float sm[];
    float* afr = sm;              // A fragments [mf 8][ks 32][lane 32][4]
    float* es  = sm + AFRAG;      // 2 x EBUF (E frags); reused for z staging / merge

    const int tid  = threadIdx.x;
    const int lane = tid & 31;
    const int warp = tid >> 5;
    const int wr   = warp >> 2;   // warp row (0..1) -> 64 token rows
    const int wn   = warp & 3;    // warp col (0..3) -> 32 codes
    const int m0   = blockIdx.x * BM;

    // ---- stage z into tf32 A-fragment layout (two 128-dim halves) ----
    for (int h = 0; h < 2; h++) {
        for (int i = tid; i < 128 * 32; i += 256) {
            int row = i >> 5, dq = i & 31;
            float4 v = __ldg(reinterpret_cast<const float4*>(
                z + (size_t)(m0 + row) * DIM + h * 128 + dq * 4));
            float* d = es + row * ZPITCH + dq * 4;
            d[0] = __uint_as_float(tf32_bits(v.x));
            d[1] = __uint_as_float(tf32_bits(v.y));
            d[2] = __uint_as_float(tf32_bits(v.z));
            d[3] = __uint_as_float(tf32_bits(v.w));
        }
        __syncthreads();
        for (int s = tid; s < 4096; s += 256) {
            int ls = s & 31, ksl = (s >> 5) & 15, mf = s >> 9;
            int r = ls >> 2, cc = ls & 3;
            const float* zb  = es + (mf * 16 + r) * ZPITCH;
            const float* zb8 = zb + 8 * ZPITCH;
            int d0 = ksl * 8 + cc;
            float4 w = make_float4(zb[d0], zb8[d0], zb[d0 + 4], zb8[d0 + 4]);
            *reinterpret_cast<float4*>(
                afr + ((mf * 32 + h * 16 + ksl) * 32 + ls) * 4) = w;
        }
        __syncthreads();
    }

    unsigned long long top[8][4];
    #pragma unroll
    for (int i = 0; i < 8; i++)
        #pragma unroll
        for (int j = 0; j < 4; j++) top[i][j] = 0ULL;

    #pragma unroll 1
    for (int nt = 0; nt < KC / BN; nt++) {
        // init accumulators with -esq/2 (column-dependent)
        float acc[4][4][4];
        #pragma unroll
        for (int nfl = 0; nfl < 4; nfl++) {
            int j0 = nt * BN + wn * 32 + nfl * 8 + (lane & 3) * 2;
            float v0 = __ldg(&g_esqh[j0]), v1 = __ldg(&g_esqh[j0 + 1]);
            #pragma unroll
            for (int mfl = 0; mfl < 4; mfl++) {
                acc[mfl][nfl][0] = v0; acc[mfl][nfl][1] = v1;
                acc[mfl][nfl][2] = v0; acc[mfl][nfl][3] = v1;
            }
        }

        // stage k-chunk 0 (64 dims) into buffer 0
        #pragma unroll
        for (int it = 0; it < 8; it++) {
            int idx = tid + it * 256;
            int code = idx >> 4, dq = idx & 15;
            float4 v = __ldg(reinterpret_cast<const float4*>(
                emb + (size_t)(nt * BN + code) * DIM + dq * 4));
            stage_bfrag(es, code, dq, v);
        }
        __syncthreads();

        #pragma unroll 1
        for (int c = 0; c < 4; c++) {
            const int buf = c & 1;
            float4 pre[8];
            if (c < 3) {
                #pragma unroll
                for (int it = 0; it < 8; it++) {
                    int idx = tid + it * 256;
                    int code = idx >> 4, dq = idx & 15;
                    pre[it] = __ldg(reinterpret_cast<const float4*>(
                        emb + (size_t)(nt * BN + code) * DIM + (c + 1) * 64 + dq * 4));
                }
            }
            const float* eb = es + buf * EBUF;

            // register-double-buffered fragments across k-steps
            unsigned a[2][4][4], b[2][4][2];
            {
                const int ksg0 = c * 8;
                #pragma unroll
                for (int mfl = 0; mfl < 4; mfl++) {
                    float4 av = *reinterpret_cast<const float4*>(
                        afr + (((wr * 4 + mfl) * 32 + ksg0) * 32 + lane) * 4);
                    a[0][mfl][0] = __float_as_uint(av.x);
                    a[0][mfl][1] = __float_as_uint(av.y);
                    a[0][mfl][2] = __float_as_uint(av.z);
                    a[0][mfl][3] = __float_as_uint(av.w);
                }
                #pragma unroll
                for (int p = 0; p < 2; p++) {
                    float4 q = *reinterpret_cast<const float4*>(
                        eb + (((0 * 8 + wn * 2 + p) * 32 + lane) << 2));
                    b[0][2*p][0]   = __float_as_uint(q.x);
                    b[0][2*p][1]   = __float_as_uint(q.y);
                    b[0][2*p+1][0] = __float_as_uint(q.z);
                    b[0][2*p+1][1] = __float_as_uint(q.w);
                }
            }
            #pragma unroll
            for (int ks = 0; ks < 8; ks++) {
                const int cur = ks & 1, nxt = cur ^ 1;
                if (ks < 7) {
                    const int ksg = c * 8 + ks + 1;
                    #pragma unroll
                    for (int mfl = 0; mfl < 4; mfl++) {
                        float4 av = *reinterpret_cast<const float4*>(
                            afr + (((wr * 4 + mfl) * 32 + ksg) * 32 + lane) * 4);
                        a[nxt][mfl][0] = __float_as_uint(av.x);
                        a[nxt][mfl][1] = __float_as_uint(av.y);
                        a[nxt][mfl][2] = __float_as_uint(av.z);
                        a[nxt][mfl][3] = __float_as_uint(av.w);
                    }
                    #pragma unroll
                    for (int p = 0; p < 2; p++) {
                        float4 q = *reinterpret_cast<const float4*>(
                            eb + ((((ks + 1) * 8 + wn * 2 + p) * 32 + lane) << 2));
                        b[nxt][2*p][0]   = __float_as_uint(q.x);
                        b[nxt][2*p][1]   = __float_as_uint(q.y);
                        b[nxt][2*p+1][0] = __float_as_uint(q.z);
                        b[nxt][2*p+1][1] = __float_as_uint(q.w);
                    }
                }
                #pragma unroll
                for (int mfl = 0; mfl < 4; mfl++)
                    #pragma unroll
                    for (int nfl = 0; nfl < 4; nfl++)
                        mma_tf32(acc[mfl][nfl], a[cur][mfl], b[cur][nfl]);
            }

            if (c < 3) {
                float* d0 = es + (buf ^ 1) * EBUF;
                #pragma unroll
                for (int it = 0; it < 8; it++) {
                    int idx = tid + it * 256;
                    int code = idx >> 4, dq = idx & 15;
                    stage_bfrag(d0, code, dq, pre[it]);
                }
            }
            __syncthreads();
        }

        // per-tile epilogue: insert 64 scores into per-thread top-4
        #pragma unroll
        for (int mfl = 0; mfl < 4; mfl++)
            #pragma unroll
            for (int nfl = 0; nfl < 4; nfl++)
                #pragma unroll
                for (int j = 0; j < 4; j++) {
                    float v = acc[mfl][nfl][j];
                    int col = nt * BN + wn * 32 + nfl * 8 + (lane & 3) * 2 + (j & 1);
                    int rs  = mfl * 2 + (j >> 1);
                    unsigned long long key =
                        ((unsigned long long)ford(v) << 32) | (unsigned)col;
                    INSERT4(top[rs], key);
                }
    }

    // ---- cross-thread merge: red[(owner*4+j)*128 + row] ----
    __syncthreads();
    unsigned long long* red = reinterpret_cast<unsigned long long*>(es);
    const int owner = wn * 4 + (lane & 3);
    #pragma unroll
    for (int rs = 0; rs < 8; rs++) {
        int row = wr * 64 + (rs >> 1) * 16 + (rs & 1) * 8 + (lane >> 2);
        #pragma unroll
        for (int j = 0; j < 4; j++)
            red[(owner * 4 + j) * 128 + row] = top[rs][j];
    }
    __syncthreads();
    if (tid < 128) {
        unsigned long long t[4] = {0ULL, 0ULL, 0ULL, 0ULL};
        for (int i = 0; i < 64; i++) {
            unsigned long long k = red[i * 128 + tid];
            INSERT4(t, k);
        }
        int row = m0 + tid;
        g_cand[0 * NTOK + row] = (int)(t[0] & 0xffffffffu);
        g_cand[1 * NTOK + row] = (int)(t[1] & 0xffffffffu);
        g_cand[2 * NTOK + row] = (int)(t[2] & 0xffffffffu);
        g_cand[3 * NTOK + row] = (int)(t[3] & 0xffffffffu);
    }
}

// ---------------- rescore: warp per token, exact reference rounding -------
__global__ __launch_bounds__(256)
void rescore_kernel(const float* __restrict__ z, const float* __restrict__ emb) {
    const int w    = (blockIdx.x * blockDim.x + threadIdx.x) >> 5;
    const int lane = threadIdx.x & 31;
    if (w >= NTOK) return;
    const float* zr = z + (size_t)w * DIM;

    float zv[8];
    #pragma unroll
    for (int j = 0; j < 8; j++) zv[j] = __ldg(&zr[j * 32 + lane]);

    // z_sq: strict sequential fp32 in index order (frozen — matches reference)
    float S = 0.0f;
    #pragma unroll
    for (int j = 0; j < 8; j++)
        for (int ii = 0; ii < 32; ii++) {
            float v = __shfl_sync(0xffffffffu, zv[j], ii);
            S = __fadd_rn(S, __fmul_rn(v, v));
        }

    float bq = 0.0f; int bi = -1;
    #pragma unroll
    for (int c = 0; c < 4; c++) {
        int idx = g_cand[c * NTOK + w];
        const float* e = emb + (size_t)idx * DIM;
        double acc = 0.0;
        #pragma unroll
        for (int j = 0; j < 8; j++)
            acc += (double)zv[j] * (double)__ldg(&e[j * 32 + lane]);
        #pragma unroll
        for (int o = 16; o; o >>= 1)
            acc += __shfl_down_sync(0xffffffffu, acc, o);
        acc = __shfl_sync(0xffffffffu, acc, 0);
        float q = __fsub_rn(__fadd_rn(S, __ldg(&g_esq[idx])),
                            __fmul_rn(2.0f, (float)acc));
        if (bi < 0 || q < bq || (q == bq && idx < bi)) { bq = q; bi = idx; }
    }
    if (lane == 0) g_indices[w] = bi;
}

// ---------------- per-token epilogue --------------------------------------
__global__ void epilogue_kernel(const float* __restrict__ z,
                                const float* __restrict__ emb,
                                float* __restrict__ out_zq,
                                float* __restrict__ out_idx) {
    int gw   = (blockIdx.x * blockDim.x + threadIdx.x) >> 5;
    int lane = threadIdx.x & 31;
    if (gw >= NTOK) return;
    int idx = g_indices[gw];
    const float4* zr = reinterpret_cast<const float4*>(z   + (size_t)gw  * DIM);
    const float4* er = reinterpret_cast<const float4*>(emb + (size_t)idx * DIM);
    float4* o = reinterpret_cast<float4*>(out_zq + (size_t)gw * DIM);
    float* esum = g_embed_sum + (size_t)idx * DIM;
    float loss = 0.0f;
    #pragma unroll
    for (int j = lane; j < DIM / 4; j += 32) {
        float4 zv = zr[j], ev = er[j];
        float dx = ev.x - zv.x, dy = ev.y - zv.y, dz = ev.z - zv.z, dw = ev.w - zv.w;
        float4 q;
        q.x = zv.x + dx; q.y = zv.y + dy; q.z = zv.z + dz; q.w = zv.w + dw;
        o[j] = q;
        loss += dx * dx + dy * dy + dz * dz + dw * dw;
        atomicAdd(&esum[j * 4 + 0], zv.x);
        atomicAdd(&esum[j * 4 + 1], zv.y);
        atomicAdd(&esum[j * 4 + 2], zv.z);
        atomicAdd(&esum[j * 4 + 3], zv.w);
    }
    #pragma unroll
    for (int off = 16; off; off >>= 1) loss += __shfl_xor_sync(0xffffffffu, loss, off);
    if (lane == 0) {
        atomicAdd(&g_loss, loss);
        atomicAdd(&g_cluster[idx], 1.0f);
        out_idx[gw] = (float)idx;
    }
}

// ---------------- EMA finalize --------------------------------------------
__global__ void finalize_kernel(const float* __restrict__ ema_cs,
                                const float* __restrict__ ema_es,
                                float* __restrict__ out_emb,
                                float* __restrict__ out_ecs,
                                float* __restrict__ out_ees,
                                float* __restrict__ out_l1,
                                float* __restrict__ out_l2) {
    int i = blockIdx.x * blockDim.x + threadIdx.x;
    if (i < KC * DIM) {
        int k = i >> 8;
        float ncs = DECAYF * ema_cs[k] + OMDF * g_cluster[k];
        float nes = DECAYF * ema_es[i] + OMDF * g_embed_sum[i];
        out_ees[i] = nes;
        out_emb[i] = nes / (ncs + EPSF);
    }
    if (i < KC) {
        out_ecs[i] = DECAYF * ema_cs[i] + OMDF * g_cluster[i];
    }
    if (i == 0) {
        float L = CWF * (g_loss / (float)(NTOK * DIM));
        out_l1[0] = L;
        out_l2[0] = L;
    }
}

// ---------------- launch ---------------------------------------------------
extern "C" void kernel_launch(void* const* d_in, const int* in_sizes, int n_in,
                              void* d_out, int out_size) {
    const float* z      = (const float*)d_in[0];
    const float* emb    = (const float*)d_in[1];
    const float* ema_cs = (const float*)d_in[2];
    const float* ema_es = (const float*)d_in[3];
    float* out = (float*)d_out;

    float* out_zq  = out;
    float* out_idx = out_zq + (size_t)NTOK * DIM;
    float* out_l1  = out_idx + NTOK;
    float* out_l2  = out_l1 + 1;
    float* out_emb = out_l2 + 1;
    float* out_ecs = out_emb + (size_t)KC * DIM;
    float* out_ees = out_ecs + KC;

    const int smem = (AFRAG + ESIZE) * 4;   // 198656 bytes
    cudaFuncSetAttribute(argmin_kernel,
                         cudaFuncAttributeMaxDynamicSharedMemorySize, smem);

    init_kernel<<<(KC * DIM + 255) / 256, 256>>>();
    esq_kernel<<<(KC * 32 + 255) / 256, 256>>>(emb);
    argmin_kernel<<<NTOK / BM, 256, smem>>>(z, emb);
    rescore_kernel<<<(NTOK * 32) / 256, 256>>>(z, emb);
    epilogue_kernel<<<(NTOK * 32 + 255) / 256, 256>>>(z, emb, out_zq, out_idx);
    finalize_kernel<<<(KC * DIM + 255) / 256, 256>>>(ema_cs, ema_es, out_emb,
                                                     out_ecs, out_ees, out_l1, out_l2);
}